// round 14
// baseline (speedup 1.0000x reference)
#include <cuda_runtime.h>
#include <cuda_bf16.h>
#include <math.h>
#include <float.h>

// Problem constants
#define BB 16
#define NN 2048
#define CC 64
#define KK 20

// Packed fp32x2 helpers (sm_103a FFMA2 path)
#define PACK2(d, lo, hi) \
    asm("mov.b64 %0, {%1, %2};" : "=l"(d) : "r"(lo), "r"(hi))
#define UNPACK2(lo, hi, s) \
    asm("mov.b64 {%0, %1}, %2;" : "=r"(lo), "=r"(hi) : "l"(s))
#define FMA2(d, a, b, c) \
    asm("fma.rn.f32x2 %0, %1, %2, %3;" : "=l"(d) : "l"(a), "l"(b), "l"(c))

// ---------------- device scratch (no runtime alloc allowed) ----------------
__device__ float g_sq[BB * NN];                 // |x|^2 per point
__device__ float g_u[BB * NN * CC];             // xi@(W1a-W1b)+b1
__device__ float g_v[BB * NN * CC];             // xj@W1b
__device__ float g_dist[(size_t)BB * NN * NN];  // 268MB pairwise distances
__device__ int   g_idx[BB * NN * KK];           // knn indices (global rows)
__device__ float g_agg[BB * NN * CC];           // max over k of MLP
__device__ float g_part[BB * 8 * CC];           // SE partial sums
__device__ float g_y[BB * CC];                  // SE gate
__device__ float g_avg[BB * NN];
__device__ float g_mx[BB * NN];

// ---------------- K0: per-point prep: sq, u, v (16 pts/block) --------------
__global__ void __launch_bounds__(256) k_prep(const float* __restrict__ x,
                                              const float* __restrict__ W1,
                                              const float* __restrict__ b1) {
    __shared__ float sW[128 * 64];   // 32KB
    __shared__ float sx[16 * 64];
    __shared__ float sred[256];
    int t = threadIdx.x;
    for (int i = t; i < 128 * 64; i += 256) sW[i] = W1[i];
    int p0 = blockIdx.x * 16;
    for (int i = t; i < 16 * 64; i += 256) sx[i] = x[p0 * 64 + i];
    __syncthreads();
    int pb = t >> 6, c = t & 63;
    float bc = b1[c];
#pragma unroll
    for (int pp = 0; pp < 4; pp++) {
        int p = pb + pp * 4;
        const float* xv = &sx[p * 64];
        float ua = 0.f, va = 0.f;
#pragma unroll 8
        for (int k = 0; k < 64; k++) {
            float xk = xv[k];
            ua += xk * sW[k * 64 + c];
            va += xk * sW[(64 + k) * 64 + c];
        }
        int row = p0 + p;
        g_u[row * 64 + c] = ua - va + bc;
        g_v[row * 64 + c] = va;
        sred[t] = xv[c] * xv[c];
        __syncthreads();
        if (c == 0) {
            float s = 0.f;
            for (int k = 0; k < 64; k++) s += sred[pb * 64 + k];
            g_sq[row] = s;
        }
        __syncthreads();
    }
}

// ---------------- K1a: pairwise distance GEMM (f32x2, 3 CTAs/SM) -----------
// grid (jt=16, it=16, b=16), 256 threads, 128x128 tile, 8x8 per thread.
// acc unpacked inline in the store phase (no 64-reg fp32 array); occupancy
// forced to 3 CTAs/SM for latency hiding.
extern __shared__ float dsm[];
__global__ void __launch_bounds__(256, 3) k_dist(const float* __restrict__ x) {
    float* As  = dsm;             // [64][132]
    float* Bs  = dsm + 8448;      // [64][132]
    float* sqi = dsm + 16896;     // 128
    float* sqj = dsm + 17024;     // 128
    int t = threadIdx.x;
    int bz = blockIdx.z;
    int it = blockIdx.y, jt = blockIdx.x;
    int base_i = (bz << 11) + it * 128;
    int base_j = (bz << 11) + jt * 128;

    for (int idx = t; idx < 8192; idx += 256) {
        int r = idx >> 6, c = idx & 63;
        As[c * 132 + r] = x[(base_i + r) * 64 + c];
        Bs[c * 132 + r] = x[(base_j + r) * 64 + c];
    }
    if (t < 128) sqi[t] = g_sq[base_i + t];
    else         sqj[t - 128] = g_sq[base_j + t - 128];
    __syncthreads();

    int tx = t & 15, ty = t >> 4;
    unsigned long long accp[8][4];
#pragma unroll
    for (int r = 0; r < 8; r++)
#pragma unroll
        for (int s = 0; s < 4; s++) accp[r][s] = 0ULL;

#pragma unroll 4
    for (int k = 0; k < 64; k++) {
        float4 a0 = *(const float4*)&As[k * 132 + ty * 4];
        float4 a1 = *(const float4*)&As[k * 132 + ty * 4 + 64];
        ulonglong2 b0 = *(const ulonglong2*)&Bs[k * 132 + tx * 4];
        ulonglong2 b1 = *(const ulonglong2*)&Bs[k * 132 + tx * 4 + 64];
        float a[8] = {a0.x, a0.y, a0.z, a0.w, a1.x, a1.y, a1.z, a1.w};
#pragma unroll
        for (int r = 0; r < 8; r++) {
            unsigned long long ap;
            unsigned int au = __float_as_uint(a[r]);
            PACK2(ap, au, au);
            FMA2(accp[r][0], ap, b0.x, accp[r][0]);
            FMA2(accp[r][1], ap, b0.y, accp[r][1]);
            FMA2(accp[r][2], ap, b1.x, accp[r][2]);
            FMA2(accp[r][3], ap, b1.y, accp[r][3]);
        }
    }

    // coalesced (i,j) write, LOCAL column base; unpack accp inline
#pragma unroll
    for (int r = 0; r < 8; r++) {
        int il = ty * 4 + (r & 3) + ((r >> 2) << 6);
        float sa = sqi[il];
        size_t rowbase = (size_t)(base_i + il) * 2048 + (size_t)(jt * 128);
#pragma unroll
        for (int sb = 0; sb < 2; sb++) {
            int jl0 = tx * 4 + (sb << 6);
            unsigned int l0, h0, l1, h1;
            UNPACK2(l0, h0, accp[r][sb * 2]);
            UNPACK2(l1, h1, accp[r][sb * 2 + 1]);
            float4 o;
            o.x = sa + sqj[jl0 + 0] - 2.f * __uint_as_float(l0);
            o.y = sa + sqj[jl0 + 1] - 2.f * __uint_as_float(h0);
            o.z = sa + sqj[jl0 + 2] - 2.f * __uint_as_float(l1);
            o.w = sa + sqj[jl0 + 3] - 2.f * __uint_as_float(h1);
            *(float4*)&g_dist[rowbase + jl0] = o;
        }
    }
}

// ---------------- K1b: top-K=20 per row via RADIX SELECT -------------------
__global__ void __launch_bounds__(256) k_topk() {
    __shared__ unsigned hist[256];
    __shared__ unsigned sh_less;
    __shared__ unsigned sh_pivot;
    __shared__ int outcnt, eqcnt;
    __shared__ int eqbuf[256];
    int row = blockIdx.x;
    int t = threadIdx.x;
    int b = row >> 11;
    const float* dr = &g_dist[(size_t)row * 2048];

    unsigned u[8];
#pragma unroll
    for (int q = 0; q < 8; q++) {
        unsigned bits = __float_as_uint(dr[t + q * 256]);
        u[q] = (bits & 0x80000000u) ? ~bits : (bits | 0x80000000u);
    }
    if (t == 0) { sh_less = 0; outcnt = 0; eqcnt = 0; }

    unsigned prefix = 0;
#pragma unroll
    for (int level = 3; level >= 0; level--) {
        hist[t] = 0;
        __syncthreads();
#pragma unroll
        for (int q = 0; q < 8; q++) {
            bool inset = (level == 3) || ((u[q] >> ((level + 1) * 8)) == prefix);
            if (inset) atomicAdd(&hist[(u[q] >> (level * 8)) & 0xFFu], 1u);
        }
        __syncthreads();
        if (t < 32) {
            unsigned cnt[8]; unsigned s = 0;
#pragma unroll
            for (int i = 0; i < 8; i++) { cnt[i] = hist[t * 8 + i]; s += cnt[i]; }
            unsigned incl = s;
#pragma unroll
            for (int o = 1; o < 32; o <<= 1) {
                unsigned v = __shfl_up_sync(0xffffffffu, incl, o);
                if (t >= o) incl += v;
            }
            unsigned c = sh_less + incl - s;
            int mybin = -1; unsigned myless = 0;
#pragma unroll
            for (int i = 0; i < 8; i++) {
                if (mybin < 0 && c + cnt[i] >= 20u) { mybin = t * 8 + i; myless = c; }
                c += cnt[i];
            }
            unsigned bal = __ballot_sync(0xffffffffu, mybin >= 0);
            int leader = __ffs((int)bal) - 1;
            if (t == leader) { sh_pivot = (unsigned)mybin; sh_less = myless; }
        }
        __syncthreads();
        prefix = (prefix << 8) | sh_pivot;
    }

    unsigned T = prefix;
#pragma unroll
    for (int q = 0; q < 8; q++) {
        int j = t + q * 256;
        if (u[q] < T) {
            int pos = atomicAdd(&outcnt, 1);
            g_idx[row * 20 + pos] = (b << 11) + j;
        } else if (u[q] == T) {
            int e = atomicAdd(&eqcnt, 1);
            if (e < 256) eqbuf[e] = j;
        }
    }
    __syncthreads();
    if (t == 0) {
        int have = outcnt;
        int nsel = 20 - have;
        int ec = eqcnt < 256 ? eqcnt : 256;
        for (int s = 0; s < nsel; s++) {
            int bi = 0x7fffffff, bpos = 0;
            for (int e = 0; e < ec; e++)
                if (eqbuf[e] < bi) { bi = eqbuf[e]; bpos = e; }
            eqbuf[bpos] = 0x7fffffff;
            g_idx[row * 20 + have + s] = (b << 11) + bi;
        }
    }
}

// ---------------- K2: edge MLP (layers 2,3) + max over k  (f32x2 packed) ---
#define PTS 8
#define EDG 160
#define EPAD 162
#define EDGE_SMEM_FLOATS 15264
extern __shared__ float esm[];
__global__ void __launch_bounds__(256) k_edge(const float* __restrict__ W2,
                                              const float* __restrict__ b2,
                                              const float* __restrict__ W3,
                                              const float* __restrict__ b3) {
    float* H   = esm;                   // [64][EPAD], reused H1 -> H2 -> H3
    float* Wr  = esm + 10368;           // [64][64]
    float* su  = esm + 14464;           // 8*64
    float* b2s = esm + 14976;
    float* b3s = esm + 15040;
    int*  sidx = (int*)(esm + 15104);   // 160

    int t = threadIdx.x;
    int base = blockIdx.x * PTS;

    for (int i = t; i < 4096; i += 256) Wr[i] = W2[i];
    su[t] = g_u[base * 64 + t];
    su[t + 256] = g_u[base * 64 + t + 256];
    if (t < 64) { b2s[t] = b2[t]; b3s[t] = b3[t]; }
    if (t < EDG) sidx[t] = g_idx[base * 20 + t];
    __syncthreads();

    for (int idx = t; idx < EDG * 64; idx += 256) {
        int e = idx >> 6, c = idx & 63;
        float val = su[(e / 20) * 64 + c] + g_v[sidx[e] * 64 + c];
        H[c * EPAD + e] = fmaxf(val, 0.f);
    }
    __syncthreads();

    int tm = t >> 4, tn = t & 15;
    unsigned long long accp[5][4];
#pragma unroll
    for (int q = 0; q < 5; q++)
#pragma unroll
        for (int s = 0; s < 4; s++) accp[q][s] = 0ULL;

#pragma unroll 2
    for (int k = 0; k < 64; k++) {
        unsigned long long a_[5];
#pragma unroll
        for (int q = 0; q < 5; q++)
            a_[q] = *(const unsigned long long*)&H[k * EPAD + 2 * tm + 32 * q];
        float4 wv = *(const float4*)&Wr[k * 64 + tn * 4];
        unsigned long long w_[4];
        {
            unsigned int uu;
            uu = __float_as_uint(wv.x); PACK2(w_[0], uu, uu);
            uu = __float_as_uint(wv.y); PACK2(w_[1], uu, uu);
            uu = __float_as_uint(wv.z); PACK2(w_[2], uu, uu);
            uu = __float_as_uint(wv.w); PACK2(w_[3], uu, uu);
        }
#pragma unroll
        for (int q = 0; q < 5; q++)
#pragma unroll
            for (int s = 0; s < 4; s++)
                FMA2(accp[q][s], a_[q], w_[s], accp[q][s]);
    }
    __syncthreads();

#pragma unroll
    for (int s = 0; s < 4; s++) {
        int n = tn * 4 + s;
        float bias = b2s[n];
#pragma unroll
        for (int q = 0; q < 5; q++) {
            unsigned int lo, hi;
            UNPACK2(lo, hi, accp[q][s]);
            float2 o;
            o.x = fmaxf(__uint_as_float(lo) + bias, 0.f);
            o.y = fmaxf(__uint_as_float(hi) + bias, 0.f);
            *(float2*)&H[n * EPAD + 2 * tm + 32 * q] = o;
            accp[q][s] = 0ULL;
        }
    }
    for (int i = t; i < 4096; i += 256) Wr[i] = W3[i];
    __syncthreads();

#pragma unroll 2
    for (int k = 0; k < 64; k++) {
        unsigned long long a_[5];
#pragma unroll
        for (int q = 0; q < 5; q++)
            a_[q] = *(const unsigned long long*)&H[k * EPAD + 2 * tm + 32 * q];
        float4 wv = *(const float4*)&Wr[k * 64 + tn * 4];
        unsigned long long w_[4];
        {
            unsigned int uu;
            uu = __float_as_uint(wv.x); PACK2(w_[0], uu, uu);
            uu = __float_as_uint(wv.y); PACK2(w_[1], uu, uu);
            uu = __float_as_uint(wv.z); PACK2(w_[2], uu, uu);
            uu = __float_as_uint(wv.w); PACK2(w_[3], uu, uu);
        }
#pragma unroll
        for (int q = 0; q < 5; q++)
#pragma unroll
            for (int s = 0; s < 4; s++)
                FMA2(accp[q][s], a_[q], w_[s], accp[q][s]);
    }
    __syncthreads();

#pragma unroll
    for (int s = 0; s < 4; s++) {
        int n = tn * 4 + s;
        float bias = b3s[n];
#pragma unroll
        for (int q = 0; q < 5; q++) {
            unsigned int lo, hi;
            UNPACK2(lo, hi, accp[q][s]);
            float2 o;
            o.x = __uint_as_float(lo) + bias;
            o.y = __uint_as_float(hi) + bias;
            *(float2*)&H[n * EPAD + 2 * tm + 32 * q] = o;
        }
    }
    __syncthreads();

    for (int idx = t; idx < PTS * 64; idx += 256) {
        int p = idx >> 6, n = idx & 63;
        const float* hp = &H[n * EPAD + p * 20];
        float m = hp[0];
#pragma unroll
        for (int kk = 1; kk < 20; kk++) m = fmaxf(m, hp[kk]);
        g_agg[(base + p) * 64 + n] = m;
    }
}

// ---------------- K3a: SE partial sums (128 blocks) ----------------
__global__ void __launch_bounds__(256) k_se1() {
    __shared__ float red[256];
    int b = blockIdx.x >> 3, chunk = blockIdx.x & 7;
    int t = threadIdx.x;
    int c = t & 63, g = t >> 6;
    int r0 = chunk * 256;
    float acc = 0.f;
    for (int r = r0 + g; r < r0 + 256; r += 4)
        acc += g_agg[((b << 11) + r) * 64 + c];
    red[t] = acc;
    __syncthreads();
    if (t < 64)
        g_part[(b * 8 + chunk) * 64 + t] =
            red[t] + red[t + 64] + red[t + 128] + red[t + 192];
}

// ---------------- K3b: SE gate finish (16 blocks) ----------------
__global__ void __launch_bounds__(64) k_se2(const float* __restrict__ se_w1,
                                            const float* __restrict__ se_w2) {
    int b = blockIdx.x, t = threadIdx.x;
    __shared__ float ss[64];
    __shared__ float rr[4];
    {
        float s = 0.f;
#pragma unroll
        for (int q = 0; q < 8; q++) s += g_part[(b * 8 + q) * 64 + t];
        ss[t] = s * (1.f / 2048.f);
    }
    __syncthreads();
    if (t < 4) {
        float a = 0.f;
        for (int cc = 0; cc < 64; cc++) a += ss[cc] * se_w1[cc * 4 + t];
        rr[t] = fmaxf(a, 0.f);
    }
    __syncthreads();
    {
        float a = 0.f;
#pragma unroll
        for (int j = 0; j < 4; j++) a += rr[j] * se_w2[j * 64 + t];
        g_y[b * 64 + t] = 1.f / (1.f + expf(-a));
    }
}

// ---------------- K4: per-row avg & max of x_se = agg*y ----------------
__global__ void __launch_bounds__(256) k_rowred() {
    int t = threadIdx.x;
    int w = t >> 5, lane = t & 31;
    int row = blockIdx.x * 8 + w;
    int b = row >> 11;
    float v1 = g_agg[row * 64 + lane] * g_y[b * 64 + lane];
    float v2 = g_agg[row * 64 + 32 + lane] * g_y[b * 64 + 32 + lane];
    float s = v1 + v2;
    float m = fmaxf(v1, v2);
#pragma unroll
    for (int o = 16; o; o >>= 1) {
        s += __shfl_down_sync(0xffffffffu, s, o);
        m = fmaxf(m, __shfl_down_sync(0xffffffffu, m, o));
    }
    if (!lane) { g_avg[row] = s * (1.f / 64.f); g_mx[row] = m; }
}

// ---------------- K5: conv1d attention + residual output ----------------
__global__ void __launch_bounds__(256) k_final(const float* __restrict__ x,
                                               const float* __restrict__ sa,
                                               float* __restrict__ out) {
    int t = threadIdx.x;
    int row = blockIdx.x * 4 + (t >> 6);
    int c = t & 63;
    int b = row >> 11, i = row & 2047;
    float acc = 0.f;
#pragma unroll
    for (int k = 0; k < 7; k++) {
        int jj = i + k - 3;
        if (jj >= 0 && jj < 2048) {
            int rj = (b << 11) + jj;
            acc += g_avg[rj] * sa[k] + g_mx[rj] * sa[7 + k];
        }
    }
    float att = 1.f / (1.f + expf(-acc));
    out[row * 64 + c] = g_agg[row * 64 + c] * g_y[b * 64 + c] * att + x[row * 64 + c];
}

// ---------------- launch ----------------
extern "C" void kernel_launch(void* const* d_in, const int* in_sizes, int n_in,
                              void* d_out, int out_size) {
    const float* x = (const float*)d_in[0];
    int wi = -1;
    for (int i = 1; i < n_in; i++) {
        if (in_sizes[i] == 8192) { wi = i; break; }
    }
    if (wi < 0) wi = 3;
    const float* W1    = (const float*)d_in[wi + 0];
    const float* b1    = (const float*)d_in[wi + 1];
    const float* W2    = (const float*)d_in[wi + 2];
    const float* b2    = (const float*)d_in[wi + 3];
    const float* W3    = (const float*)d_in[wi + 4];
    const float* b3    = (const float*)d_in[wi + 5];
    const float* se_w1 = (const float*)d_in[wi + 6];
    const float* se_w2 = (const float*)d_in[wi + 7];
    const float* sa_w  = (const float*)d_in[wi + 8];
    float* out = (float*)d_out;

    cudaFuncSetAttribute(k_dist, cudaFuncAttributeMaxDynamicSharedMemorySize, 17152 * 4);
    cudaFuncSetAttribute(k_edge, cudaFuncAttributeMaxDynamicSharedMemorySize,
                         EDGE_SMEM_FLOATS * 4);

    k_prep<<<(BB * NN) / 16, 256>>>(x, W1, b1);
    k_dist<<<dim3(16, 16, 16), 256, 17152 * 4>>>(x);
    k_topk<<<BB * NN, 256>>>();
    k_edge<<<(BB * NN) / PTS, 256, EDGE_SMEM_FLOATS * 4>>>(W2, b2, W3, b3);
    k_se1<<<BB * 8, 256>>>();
    k_se2<<<BB, 64>>>(se_w1, se_w2);
    k_rowred<<<(BB * NN) / 8, 256>>>();
    k_final<<<(BB * NN) / 4, 256>>>(x, sa_w, out);
}

// round 15
// speedup vs baseline: 1.4516x; 1.4516x over previous
#include <cuda_runtime.h>
#include <cuda_bf16.h>
#include <math.h>
#include <float.h>

// Problem constants
#define BB 16
#define NN 2048
#define CC 64
#define KK 20

// Packed fp32x2 helpers (sm_103a FFMA2 path)
#define PACK2(d, lo, hi) \
    asm("mov.b64 %0, {%1, %2};" : "=l"(d) : "r"(lo), "r"(hi))
#define UNPACK2(lo, hi, s) \
    asm("mov.b64 {%0, %1}, %2;" : "=r"(lo), "=r"(hi) : "l"(s))
#define FMA2(d, a, b, c) \
    asm("fma.rn.f32x2 %0, %1, %2, %3;" : "=l"(d) : "l"(a), "l"(b), "l"(c))

// ---------------- device scratch (no runtime alloc allowed) ----------------
__device__ float g_sq[BB * NN];                 // |x|^2 per point
__device__ float g_u[BB * NN * CC];             // xi@(W1a-W1b)+b1
__device__ float g_v[BB * NN * CC];             // xj@W1b
__device__ float g_dist[(size_t)BB * NN * NN];  // 268MB pairwise distances
__device__ int   g_idx[BB * NN * KK];           // knn indices (global rows)
__device__ float g_agg[BB * NN * CC];           // max over k of MLP
__device__ float g_part[BB * 8 * CC];           // SE partial sums
__device__ float g_y[BB * CC];                  // SE gate
__device__ float g_avg[BB * NN];
__device__ float g_mx[BB * NN];

// ---------------- K0: per-point prep: sq, u, v (16 pts/block) --------------
__global__ void __launch_bounds__(256) k_prep(const float* __restrict__ x,
                                              const float* __restrict__ W1,
                                              const float* __restrict__ b1) {
    __shared__ float sW[128 * 64];   // 32KB
    __shared__ float sx[16 * 64];
    __shared__ float sred[256];
    int t = threadIdx.x;
    for (int i = t; i < 128 * 64; i += 256) sW[i] = W1[i];
    int p0 = blockIdx.x * 16;
    for (int i = t; i < 16 * 64; i += 256) sx[i] = x[p0 * 64 + i];
    __syncthreads();
    int pb = t >> 6, c = t & 63;
    float bc = b1[c];
#pragma unroll
    for (int pp = 0; pp < 4; pp++) {
        int p = pb + pp * 4;
        const float* xv = &sx[p * 64];
        float ua = 0.f, va = 0.f;
#pragma unroll 8
        for (int k = 0; k < 64; k++) {
            float xk = xv[k];
            ua += xk * sW[k * 64 + c];
            va += xk * sW[(64 + k) * 64 + c];
        }
        int row = p0 + p;
        g_u[row * 64 + c] = ua - va + bc;
        g_v[row * 64 + c] = va;
        sred[t] = xv[c] * xv[c];
        __syncthreads();
        if (c == 0) {
            float s = 0.f;
            for (int k = 0; k < 64; k++) s += sred[pb * 64 + k];
            g_sq[row] = s;
        }
        __syncthreads();
    }
}

// ---------------- K1a: pairwise distance GEMM (f32x2, r13 exact) -----------
// grid (jt=16, it=16, b=16), 256 threads, 128x128 tile, 8x8 per thread.
// Natural occupancy (NO forced launch_bounds minimum — r14's forced 3 CTAs/SM
// caused register spills and a 2x dist regression).
extern __shared__ float dsm[];
__global__ void __launch_bounds__(256) k_dist(const float* __restrict__ x) {
    float* As  = dsm;             // [64][132]
    float* Bs  = dsm + 8448;      // [64][132]
    float* sqi = dsm + 16896;     // 128
    float* sqj = dsm + 17024;     // 128
    int t = threadIdx.x;
    int bz = blockIdx.z;
    int it = blockIdx.y, jt = blockIdx.x;
    int base_i = (bz << 11) + it * 128;
    int base_j = (bz << 11) + jt * 128;

    for (int idx = t; idx < 8192; idx += 256) {
        int r = idx >> 6, c = idx & 63;
        As[c * 132 + r] = x[(base_i + r) * 64 + c];
        Bs[c * 132 + r] = x[(base_j + r) * 64 + c];
    }
    if (t < 128) sqi[t] = g_sq[base_i + t];
    else         sqj[t - 128] = g_sq[base_j + t - 128];
    __syncthreads();

    int tx = t & 15, ty = t >> 4;
    unsigned long long accp[8][4];
#pragma unroll
    for (int r = 0; r < 8; r++)
#pragma unroll
        for (int s = 0; s < 4; s++) accp[r][s] = 0ULL;

#pragma unroll 4
    for (int k = 0; k < 64; k++) {
        float4 a0 = *(const float4*)&As[k * 132 + ty * 4];
        float4 a1 = *(const float4*)&As[k * 132 + ty * 4 + 64];
        ulonglong2 b0 = *(const ulonglong2*)&Bs[k * 132 + tx * 4];
        ulonglong2 b1 = *(const ulonglong2*)&Bs[k * 132 + tx * 4 + 64];
        float a[8] = {a0.x, a0.y, a0.z, a0.w, a1.x, a1.y, a1.z, a1.w};
#pragma unroll
        for (int r = 0; r < 8; r++) {
            unsigned long long ap;
            unsigned int au = __float_as_uint(a[r]);
            PACK2(ap, au, au);
            FMA2(accp[r][0], ap, b0.x, accp[r][0]);
            FMA2(accp[r][1], ap, b0.y, accp[r][1]);
            FMA2(accp[r][2], ap, b1.x, accp[r][2]);
            FMA2(accp[r][3], ap, b1.y, accp[r][3]);
        }
    }

    float acc[8][8];
#pragma unroll
    for (int r = 0; r < 8; r++)
#pragma unroll
        for (int sp = 0; sp < 4; sp++) {
            unsigned int lo, hi;
            UNPACK2(lo, hi, accp[r][sp]);
            acc[r][sp * 2]     = __uint_as_float(lo);
            acc[r][sp * 2 + 1] = __uint_as_float(hi);
        }

#pragma unroll
    for (int r = 0; r < 8; r++) {
        int il = ty * 4 + (r & 3) + ((r >> 2) << 6);
        float sa = sqi[il];
        size_t rowbase = (size_t)(base_i + il) * 2048 + (size_t)(jt * 128);
#pragma unroll
        for (int sb = 0; sb < 2; sb++) {
            int jl0 = tx * 4 + (sb << 6);
            float4 o;
            o.x = sa + sqj[jl0 + 0] - 2.f * acc[r][sb * 4 + 0];
            o.y = sa + sqj[jl0 + 1] - 2.f * acc[r][sb * 4 + 1];
            o.z = sa + sqj[jl0 + 2] - 2.f * acc[r][sb * 4 + 2];
            o.w = sa + sqj[jl0 + 3] - 2.f * acc[r][sb * 4 + 3];
            *(float4*)&g_dist[rowbase + jl0] = o;
        }
    }
}

// ---------------- K1b: top-K=20 per row via RADIX SELECT -------------------
__global__ void __launch_bounds__(256) k_topk() {
    __shared__ unsigned hist[256];
    __shared__ unsigned sh_less;
    __shared__ unsigned sh_pivot;
    __shared__ int outcnt, eqcnt;
    __shared__ int eqbuf[256];
    int row = blockIdx.x;
    int t = threadIdx.x;
    int b = row >> 11;
    const float* dr = &g_dist[(size_t)row * 2048];

    unsigned u[8];
#pragma unroll
    for (int q = 0; q < 8; q++) {
        unsigned bits = __float_as_uint(dr[t + q * 256]);
        u[q] = (bits & 0x80000000u) ? ~bits : (bits | 0x80000000u);
    }
    if (t == 0) { sh_less = 0; outcnt = 0; eqcnt = 0; }

    unsigned prefix = 0;
#pragma unroll
    for (int level = 3; level >= 0; level--) {
        hist[t] = 0;
        __syncthreads();
#pragma unroll
        for (int q = 0; q < 8; q++) {
            bool inset = (level == 3) || ((u[q] >> ((level + 1) * 8)) == prefix);
            if (inset) atomicAdd(&hist[(u[q] >> (level * 8)) & 0xFFu], 1u);
        }
        __syncthreads();
        if (t < 32) {
            unsigned cnt[8]; unsigned s = 0;
#pragma unroll
            for (int i = 0; i < 8; i++) { cnt[i] = hist[t * 8 + i]; s += cnt[i]; }
            unsigned incl = s;
#pragma unroll
            for (int o = 1; o < 32; o <<= 1) {
                unsigned v = __shfl_up_sync(0xffffffffu, incl, o);
                if (t >= o) incl += v;
            }
            unsigned c = sh_less + incl - s;
            int mybin = -1; unsigned myless = 0;
#pragma unroll
            for (int i = 0; i < 8; i++) {
                if (mybin < 0 && c + cnt[i] >= 20u) { mybin = t * 8 + i; myless = c; }
                c += cnt[i];
            }
            unsigned bal = __ballot_sync(0xffffffffu, mybin >= 0);
            int leader = __ffs((int)bal) - 1;
            if (t == leader) { sh_pivot = (unsigned)mybin; sh_less = myless; }
        }
        __syncthreads();
        prefix = (prefix << 8) | sh_pivot;
    }

    unsigned T = prefix;
#pragma unroll
    for (int q = 0; q < 8; q++) {
        int j = t + q * 256;
        if (u[q] < T) {
            int pos = atomicAdd(&outcnt, 1);
            g_idx[row * 20 + pos] = (b << 11) + j;
        } else if (u[q] == T) {
            int e = atomicAdd(&eqcnt, 1);
            if (e < 256) eqbuf[e] = j;
        }
    }
    __syncthreads();
    if (t == 0) {
        int have = outcnt;
        int nsel = 20 - have;
        int ec = eqcnt < 256 ? eqcnt : 256;
        for (int s = 0; s < nsel; s++) {
            int bi = 0x7fffffff, bpos = 0;
            for (int e = 0; e < ec; e++)
                if (eqbuf[e] < bi) { bi = eqbuf[e]; bpos = e; }
            eqbuf[bpos] = 0x7fffffff;
            g_idx[row * 20 + have + s] = (b << 11) + bi;
        }
    }
}

// ---------------- K2: edge MLP (layers 2,3) + max over k  (f32x2 packed) ---
#define PTS 8
#define EDG 160
#define EPAD 162
#define EDGE_SMEM_FLOATS 15264
extern __shared__ float esm[];
__global__ void __launch_bounds__(256) k_edge(const float* __restrict__ W2,
                                              const float* __restrict__ b2,
                                              const float* __restrict__ W3,
                                              const float* __restrict__ b3) {
    float* H   = esm;                   // [64][EPAD], reused H1 -> H2 -> H3
    float* Wr  = esm + 10368;           // [64][64]
    float* su  = esm + 14464;           // 8*64
    float* b2s = esm + 14976;
    float* b3s = esm + 15040;
    int*  sidx = (int*)(esm + 15104);   // 160

    int t = threadIdx.x;
    int base = blockIdx.x * PTS;

    for (int i = t; i < 4096; i += 256) Wr[i] = W2[i];
    su[t] = g_u[base * 64 + t];
    su[t + 256] = g_u[base * 64 + t + 256];
    if (t < 64) { b2s[t] = b2[t]; b3s[t] = b3[t]; }
    if (t < EDG) sidx[t] = g_idx[base * 20 + t];
    __syncthreads();

    for (int idx = t; idx < EDG * 64; idx += 256) {
        int e = idx >> 6, c = idx & 63;
        float val = su[(e / 20) * 64 + c] + g_v[sidx[e] * 64 + c];
        H[c * EPAD + e] = fmaxf(val, 0.f);
    }
    __syncthreads();

    int tm = t >> 4, tn = t & 15;
    unsigned long long accp[5][4];
#pragma unroll
    for (int q = 0; q < 5; q++)
#pragma unroll
        for (int s = 0; s < 4; s++) accp[q][s] = 0ULL;

#pragma unroll 2
    for (int k = 0; k < 64; k++) {
        unsigned long long a_[5];
#pragma unroll
        for (int q = 0; q < 5; q++)
            a_[q] = *(const unsigned long long*)&H[k * EPAD + 2 * tm + 32 * q];
        float4 wv = *(const float4*)&Wr[k * 64 + tn * 4];
        unsigned long long w_[4];
        {
            unsigned int uu;
            uu = __float_as_uint(wv.x); PACK2(w_[0], uu, uu);
            uu = __float_as_uint(wv.y); PACK2(w_[1], uu, uu);
            uu = __float_as_uint(wv.z); PACK2(w_[2], uu, uu);
            uu = __float_as_uint(wv.w); PACK2(w_[3], uu, uu);
        }
#pragma unroll
        for (int q = 0; q < 5; q++)
#pragma unroll
            for (int s = 0; s < 4; s++)
                FMA2(accp[q][s], a_[q], w_[s], accp[q][s]);
    }
    __syncthreads();

#pragma unroll
    for (int s = 0; s < 4; s++) {
        int n = tn * 4 + s;
        float bias = b2s[n];
#pragma unroll
        for (int q = 0; q < 5; q++) {
            unsigned int lo, hi;
            UNPACK2(lo, hi, accp[q][s]);
            float2 o;
            o.x = fmaxf(__uint_as_float(lo) + bias, 0.f);
            o.y = fmaxf(__uint_as_float(hi) + bias, 0.f);
            *(float2*)&H[n * EPAD + 2 * tm + 32 * q] = o;
            accp[q][s] = 0ULL;
        }
    }
    for (int i = t; i < 4096; i += 256) Wr[i] = W3[i];
    __syncthreads();

#pragma unroll 2
    for (int k = 0; k < 64; k++) {
        unsigned long long a_[5];
#pragma unroll
        for (int q = 0; q < 5; q++)
            a_[q] = *(const unsigned long long*)&H[k * EPAD + 2 * tm + 32 * q];
        float4 wv = *(const float4*)&Wr[k * 64 + tn * 4];
        unsigned long long w_[4];
        {
            unsigned int uu;
            uu = __float_as_uint(wv.x); PACK2(w_[0], uu, uu);
            uu = __float_as_uint(wv.y); PACK2(w_[1], uu, uu);
            uu = __float_as_uint(wv.z); PACK2(w_[2], uu, uu);
            uu = __float_as_uint(wv.w); PACK2(w_[3], uu, uu);
        }
#pragma unroll
        for (int q = 0; q < 5; q++)
#pragma unroll
            for (int s = 0; s < 4; s++)
                FMA2(accp[q][s], a_[q], w_[s], accp[q][s]);
    }
    __syncthreads();

#pragma unroll
    for (int s = 0; s < 4; s++) {
        int n = tn * 4 + s;
        float bias = b3s[n];
#pragma unroll
        for (int q = 0; q < 5; q++) {
            unsigned int lo, hi;
            UNPACK2(lo, hi, accp[q][s]);
            float2 o;
            o.x = __uint_as_float(lo) + bias;
            o.y = __uint_as_float(hi) + bias;
            *(float2*)&H[n * EPAD + 2 * tm + 32 * q] = o;
        }
    }
    __syncthreads();

    for (int idx = t; idx < PTS * 64; idx += 256) {
        int p = idx >> 6, n = idx & 63;
        const float* hp = &H[n * EPAD + p * 20];
        float m = hp[0];
#pragma unroll
        for (int kk = 1; kk < 20; kk++) m = fmaxf(m, hp[kk]);
        g_agg[(base + p) * 64 + n] = m;
    }
}

// ---------------- K3a: SE partial sums (128 blocks) ----------------
__global__ void __launch_bounds__(256) k_se1() {
    __shared__ float red[256];
    int b = blockIdx.x >> 3, chunk = blockIdx.x & 7;
    int t = threadIdx.x;
    int c = t & 63, g = t >> 6;
    int r0 = chunk * 256;
    float acc = 0.f;
    for (int r = r0 + g; r < r0 + 256; r += 4)
        acc += g_agg[((b << 11) + r) * 64 + c];
    red[t] = acc;
    __syncthreads();
    if (t < 64)
        g_part[(b * 8 + chunk) * 64 + t] =
            red[t] + red[t + 64] + red[t + 128] + red[t + 192];
}

// ---------------- K3b: SE gate finish (16 blocks) ----------------
__global__ void __launch_bounds__(64) k_se2(const float* __restrict__ se_w1,
                                            const float* __restrict__ se_w2) {
    int b = blockIdx.x, t = threadIdx.x;
    __shared__ float ss[64];
    __shared__ float rr[4];
    {
        float s = 0.f;
#pragma unroll
        for (int q = 0; q < 8; q++) s += g_part[(b * 8 + q) * 64 + t];
        ss[t] = s * (1.f / 2048.f);
    }
    __syncthreads();
    if (t < 4) {
        float a = 0.f;
        for (int cc = 0; cc < 64; cc++) a += ss[cc] * se_w1[cc * 4 + t];
        rr[t] = fmaxf(a, 0.f);
    }
    __syncthreads();
    {
        float a = 0.f;
#pragma unroll
        for (int j = 0; j < 4; j++) a += rr[j] * se_w2[j * 64 + t];
        g_y[b * 64 + t] = 1.f / (1.f + expf(-a));
    }
}

// ---------------- K4: per-row avg & max of x_se = agg*y ----------------
__global__ void __launch_bounds__(256) k_rowred() {
    int t = threadIdx.x;
    int w = t >> 5, lane = t & 31;
    int row = blockIdx.x * 8 + w;
    int b = row >> 11;
    float v1 = g_agg[row * 64 + lane] * g_y[b * 64 + lane];
    float v2 = g_agg[row * 64 + 32 + lane] * g_y[b * 64 + 32 + lane];
    float s = v1 + v2;
    float m = fmaxf(v1, v2);
#pragma unroll
    for (int o = 16; o; o >>= 1) {
        s += __shfl_down_sync(0xffffffffu, s, o);
        m = fmaxf(m, __shfl_down_sync(0xffffffffu, m, o));
    }
    if (!lane) { g_avg[row] = s * (1.f / 64.f); g_mx[row] = m; }
}

// ---------------- K5: conv1d attention + residual output ----------------
__global__ void __launch_bounds__(256) k_final(const float* __restrict__ x,
                                               const float* __restrict__ sa,
                                               float* __restrict__ out) {
    int t = threadIdx.x;
    int row = blockIdx.x * 4 + (t >> 6);
    int c = t & 63;
    int b = row >> 11, i = row & 2047;
    float acc = 0.f;
#pragma unroll
    for (int k = 0; k < 7; k++) {
        int jj = i + k - 3;
        if (jj >= 0 && jj < 2048) {
            int rj = (b << 11) + jj;
            acc += g_avg[rj] * sa[k] + g_mx[rj] * sa[7 + k];
        }
    }
    float att = 1.f / (1.f + expf(-acc));
    out[row * 64 + c] = g_agg[row * 64 + c] * g_y[b * 64 + c] * att + x[row * 64 + c];
}

// ---------------- launch ----------------
extern "C" void kernel_launch(void* const* d_in, const int* in_sizes, int n_in,
                              void* d_out, int out_size) {
    const float* x = (const float*)d_in[0];
    int wi = -1;
    for (int i = 1; i < n_in; i++) {
        if (in_sizes[i] == 8192) { wi = i; break; }
    }
    if (wi < 0) wi = 3;
    const float* W1    = (const float*)d_in[wi + 0];
    const float* b1    = (const float*)d_in[wi + 1];
    const float* W2    = (const float*)d_in[wi + 2];
    const float* b2    = (const float*)d_in[wi + 3];
    const float* W3    = (const float*)d_in[wi + 4];
    const float* b3    = (const float*)d_in[wi + 5];
    const float* se_w1 = (const float*)d_in[wi + 6];
    const float* se_w2 = (const float*)d_in[wi + 7];
    const float* sa_w  = (const float*)d_in[wi + 8];
    float* out = (float*)d_out;

    cudaFuncSetAttribute(k_dist, cudaFuncAttributeMaxDynamicSharedMemorySize, 17152 * 4);
    cudaFuncSetAttribute(k_edge, cudaFuncAttributeMaxDynamicSharedMemorySize,
                         EDGE_SMEM_FLOATS * 4);

    k_prep<<<(BB * NN) / 16, 256>>>(x, W1, b1);
    k_dist<<<dim3(16, 16, 16), 256, 17152 * 4>>>(x);
    k_topk<<<BB * NN, 256>>>();
    k_edge<<<(BB * NN) / PTS, 256, EDGE_SMEM_FLOATS * 4>>>(W2, b2, W3, b3);
    k_se1<<<BB * 8, 256>>>();
    k_se2<<<BB, 64>>>(se_w1, se_w2);
    k_rowred<<<(BB * NN) / 8, 256>>>();
    k_final<<<(BB * NN) / 4, 256>>>(x, sa_w, out);
}